// round 1
// baseline (speedup 1.0000x reference)
#include <cuda_runtime.h>

#define THREADS 256

__device__ __forceinline__ float2 cmul(float2 a, float2 b) {
    return make_float2(fmaf(a.x, b.x, -a.y * b.y), fmaf(a.x, b.y, a.y * b.x));
}

// Pad every 4 words with 1 extra word: kills the stride-4m bank conflicts of the
// Stockham strided writes while keeping consecutive reads ~conflict-free.
__device__ __forceinline__ int pad(int w) { return w + (w >> 2); }

// Radix-4 DIF butterfly (forward): in-place on c0..c3 (pre-twiddle outputs)
__device__ __forceinline__ void bfly4(float2& c0, float2& c1, float2& c2, float2& c3) {
    float2 t0 = make_float2(c0.x + c2.x, c0.y + c2.y);
    float2 t2 = make_float2(c0.x - c2.x, c0.y - c2.y);
    float2 t1 = make_float2(c1.x + c3.x, c1.y + c3.y);
    float2 u  = make_float2(c1.x - c3.x, c1.y - c3.y);
    float2 t3 = make_float2(u.y, -u.x);  // -i * (c1 - c3)
    c0 = make_float2(t0.x + t1.x, t0.y + t1.y);
    c1 = make_float2(t2.x + t3.x, t2.y + t3.y);
    c2 = make_float2(t0.x - t1.x, t0.y - t1.y);
    c3 = make_float2(t2.x - t3.x, t2.y - t3.y);
}

__device__ __forceinline__ void twiddle3(float2& c1, float2& c2, float2& c3, float ang) {
    float s, c;
    __sincosf(ang, &s, &c);
    float2 w1 = make_float2(c, s);
    float2 w2 = cmul(w1, w1);
    float2 w3 = cmul(w2, w1);
    c1 = cmul(c1, w1);
    c2 = cmul(c2, w2);
    c3 = cmul(c3, w3);
}

// One CTA per batch row. 1024-pt complex FFT, radix-4 Stockham autosort:
//   stage (l, m): read  idx = k + j*m + q*l*m  (== t + 256*q for all stages)
//                 write idx = k + 4*j*m + q*m
//   (l,m): (256,1) -> (64,4) -> (16,16) -> (4,64) -> (1,256)
// Stage 1 reads global, stage 5 writes global (twiddle = 1 there).
__global__ void __launch_bounds__(THREADS) fft1024_kernel(
    const float* __restrict__ xin, float* __restrict__ xout)
{
    __shared__ float sre[2][1280];
    __shared__ float sim[2][1280];

    const int t = threadIdx.x;
    const float2* __restrict__ xb =
        reinterpret_cast<const float2*>(xin) + (size_t)blockIdx.x * 1024;
    float2* __restrict__ yb =
        reinterpret_cast<float2*>(xout) + (size_t)blockIdx.x * 1024;

    const float NEG2PI = -6.28318530717958647692f;

    // ---------------- Stage 1: l=256, m=1, j=t, k=0 (global -> smem[0]) ----
    float2 c0 = xb[t];
    float2 c1 = xb[t + 256];
    float2 c2 = xb[t + 512];
    float2 c3 = xb[t + 768];
    bfly4(c0, c1, c2, c3);
    twiddle3(c1, c2, c3, NEG2PI * (float)t * (1.0f / 1024.0f));
    {
        int w = 4 * t;
        sre[0][pad(w + 0)] = c0.x; sim[0][pad(w + 0)] = c0.y;
        sre[0][pad(w + 1)] = c1.x; sim[0][pad(w + 1)] = c1.y;
        sre[0][pad(w + 2)] = c2.x; sim[0][pad(w + 2)] = c2.y;
        sre[0][pad(w + 3)] = c3.x; sim[0][pad(w + 3)] = c3.y;
    }
    __syncthreads();

    // ---------------- Stage 2: l=64, m=4, j=t>>2, k=t&3 (smem[0]->smem[1]) --
    c0 = make_float2(sre[0][pad(t)],       sim[0][pad(t)]);
    c1 = make_float2(sre[0][pad(t + 256)], sim[0][pad(t + 256)]);
    c2 = make_float2(sre[0][pad(t + 512)], sim[0][pad(t + 512)]);
    c3 = make_float2(sre[0][pad(t + 768)], sim[0][pad(t + 768)]);
    bfly4(c0, c1, c2, c3);
    twiddle3(c1, c2, c3, NEG2PI * (float)(t >> 2) * (1.0f / 256.0f));
    {
        int w = (t & 3) + ((t >> 2) << 4);
        sre[1][pad(w + 0)]  = c0.x; sim[1][pad(w + 0)]  = c0.y;
        sre[1][pad(w + 4)]  = c1.x; sim[1][pad(w + 4)]  = c1.y;
        sre[1][pad(w + 8)]  = c2.x; sim[1][pad(w + 8)]  = c2.y;
        sre[1][pad(w + 12)] = c3.x; sim[1][pad(w + 12)] = c3.y;
    }
    __syncthreads();

    // ---------------- Stage 3: l=16, m=16, j=t>>4, k=t&15 (smem[1]->smem[0])
    c0 = make_float2(sre[1][pad(t)],       sim[1][pad(t)]);
    c1 = make_float2(sre[1][pad(t + 256)], sim[1][pad(t + 256)]);
    c2 = make_float2(sre[1][pad(t + 512)], sim[1][pad(t + 512)]);
    c3 = make_float2(sre[1][pad(t + 768)], sim[1][pad(t + 768)]);
    bfly4(c0, c1, c2, c3);
    twiddle3(c1, c2, c3, NEG2PI * (float)(t >> 4) * (1.0f / 64.0f));
    {
        int w = (t & 15) + ((t >> 4) << 6);
        sre[0][pad(w + 0)]  = c0.x; sim[0][pad(w + 0)]  = c0.y;
        sre[0][pad(w + 16)] = c1.x; sim[0][pad(w + 16)] = c1.y;
        sre[0][pad(w + 32)] = c2.x; sim[0][pad(w + 32)] = c2.y;
        sre[0][pad(w + 48)] = c3.x; sim[0][pad(w + 48)] = c3.y;
    }
    __syncthreads();

    // ---------------- Stage 4: l=4, m=64, j=t>>6, k=t&63 (smem[0]->smem[1]) -
    c0 = make_float2(sre[0][pad(t)],       sim[0][pad(t)]);
    c1 = make_float2(sre[0][pad(t + 256)], sim[0][pad(t + 256)]);
    c2 = make_float2(sre[0][pad(t + 512)], sim[0][pad(t + 512)]);
    c3 = make_float2(sre[0][pad(t + 768)], sim[0][pad(t + 768)]);
    bfly4(c0, c1, c2, c3);
    twiddle3(c1, c2, c3, NEG2PI * (float)(t >> 6) * (1.0f / 16.0f));
    {
        int w = (t & 63) + ((t >> 6) << 8);
        sre[1][pad(w + 0)]   = c0.x; sim[1][pad(w + 0)]   = c0.y;
        sre[1][pad(w + 64)]  = c1.x; sim[1][pad(w + 64)]  = c1.y;
        sre[1][pad(w + 128)] = c2.x; sim[1][pad(w + 128)] = c2.y;
        sre[1][pad(w + 192)] = c3.x; sim[1][pad(w + 192)] = c3.y;
    }
    __syncthreads();

    // ---------------- Stage 5: l=1, m=256, j=0 twiddle=1 (smem[1]->global) --
    c0 = make_float2(sre[1][pad(t)],       sim[1][pad(t)]);
    c1 = make_float2(sre[1][pad(t + 256)], sim[1][pad(t + 256)]);
    c2 = make_float2(sre[1][pad(t + 512)], sim[1][pad(t + 512)]);
    c3 = make_float2(sre[1][pad(t + 768)], sim[1][pad(t + 768)]);
    bfly4(c0, c1, c2, c3);
    yb[t]       = c0;
    yb[t + 256] = c1;
    yb[t + 512] = c2;
    yb[t + 768] = c3;
}

extern "C" void kernel_launch(void* const* d_in, const int* in_sizes, int n_in,
                              void* d_out, int out_size)
{
    const float* x = (const float*)d_in[0];
    float* y = (float*)d_out;
    const int B = in_sizes[0] / 2048;  // 1024 complex (2048 floats) per row
    fft1024_kernel<<<B, THREADS>>>(x, y);
}

// round 2
// speedup vs baseline: 1.2863x; 1.2863x over previous
#include <cuda_runtime.h>

#define WARPS_PER_CTA 4
#define THREADS (WARPS_PER_CTA * 32)

// bit-reversal of 5 bits
__device__ __constant__ int BR5_[32]; // unused; compile-time table below

// 32-point radix-2 DIF FFT, in place. Input natural order, output bit-reversed:
// after the call, (ar[i], ai[i]) = X[bitrev5(i)].
// All stage twiddles are the 16 compile-time constants e^{-2*pi*i*j/32}.
__device__ __forceinline__ void fft32(float* ar, float* ai)
{
    constexpr float TWC[16] = {
        1.0f, 0.980785280f, 0.923879533f, 0.831469612f,
        0.707106781f, 0.555570233f, 0.382683432f, 0.195090322f,
        0.0f, -0.195090322f, -0.382683432f, -0.555570233f,
        -0.707106781f, -0.831469612f, -0.923879533f, -0.980785280f };
    constexpr float TWS[16] = {
        0.0f, -0.195090322f, -0.382683432f, -0.555570233f,
        -0.707106781f, -0.831469612f, -0.923879533f, -0.980785280f,
        -1.0f, -0.980785280f, -0.923879533f, -0.831469612f,
        -0.707106781f, -0.555570233f, -0.382683432f, -0.195090322f };

#pragma unroll
    for (int s = 0; s < 5; s++) {
        const int span = 16 >> s;      // butterfly distance
        const int tstep = 1 << s;      // twiddle index stride
#pragma unroll
        for (int b = 0; b < 32; b += 2 * span) {
#pragma unroll
            for (int j = 0; j < span; j++) {
                const int i0 = b + j;
                const int i1 = b + j + span;
                float ur = ar[i0], ui = ai[i0];
                float vr = ar[i1], vi = ai[i1];
                ar[i0] = ur + vr;
                ai[i0] = ui + vi;
                float dr = ur - vr;
                float di = ui - vi;
                const float wr = TWC[j * tstep];
                const float wi = TWS[j * tstep];
                ar[i1] = dr * wr - di * wi;
                ai[i1] = dr * wi + di * wr;
            }
        }
    }
}

// Four-step 1024-pt complex FFT: 1024 = 32 (n1/k2 dim) x 32 (n2/k1 dim).
//   X[k1 + 32*k2] = DFT32_{n1}( W1024^{n1*k1} * DFT32_{n2}( x[32*n2 + n1] ) )
// One warp per batch row; lane = n1 in phase A, lane = k1 in phase B.
// Single padded smem transpose between phases, conflict-free both ways.
__global__ void __launch_bounds__(THREADS) fft1024_kernel(
    const float* __restrict__ xin, float* __restrict__ xout)
{
    __shared__ float sre[WARPS_PER_CTA][32 * 33];
    __shared__ float sim[WARPS_PER_CTA][32 * 33];

    const int lane = threadIdx.x & 31;
    const int w = threadIdx.x >> 5;
    const int row = blockIdx.x * WARPS_PER_CTA + w;

    const float2* __restrict__ xb =
        reinterpret_cast<const float2*>(xin) + (size_t)row * 1024;
    float2* __restrict__ yb =
        reinterpret_cast<float2*>(xout) + (size_t)row * 1024;

    float ar[32], ai[32];

    // ---- Phase A load: lane t holds column n1=t, a[n2] = x[32*n2 + t] ----
    // (coalesced: 256B per n2 across the warp)
#pragma unroll
    for (int n2 = 0; n2 < 32; n2++) {
        float2 v = __ldcs(&xb[n2 * 32 + lane]);
        ar[n2] = v.x;
        ai[n2] = v.y;
    }

    // ---- Phase A FFT over n2 ----
    fft32(ar, ai);  // (ar[i],ai[i]) = Y[n1=lane][k1=bitrev(i)]

    // ---- Twiddle by W1024^{n1*k1} and store transposed ----
    const float base = -6.2831853071795864769f / 1024.0f * (float)lane;
#pragma unroll
    for (int i = 0; i < 32; i++) {
        // bitrev5(i), compile-time constant after unroll
        const int k1 = ((i & 1) << 4) | ((i & 2) << 2) | (i & 4) |
                       ((i & 8) >> 2) | ((i & 16) >> 4);
        float c, s;
        if (k1 == 0) { c = 1.0f; s = 0.0f; }
        else __sincosf(base * (float)k1, &s, &c);
        const float tr = ar[i] * c - ai[i] * s;
        const float ti = ar[i] * s + ai[i] * c;
        sre[w][k1 * 33 + lane] = tr;   // smem[k1][n1]
        sim[w][k1 * 33 + lane] = ti;
    }
    __syncwarp();

    // ---- Transposed reload: lane t = k1, b[n1] = Z[n1][k1=t] ----
#pragma unroll
    for (int n1 = 0; n1 < 32; n1++) {
        ar[n1] = sre[w][lane * 33 + n1];
        ai[n1] = sim[w][lane * 33 + n1];
    }

    // ---- Phase B FFT over n1 ----
    fft32(ar, ai);  // (ar[i],ai[i]) = X[k1=lane + 32*k2], k2 = bitrev(i)

    // ---- Write out: X[lane + 32*bitrev(i)] (coalesced per i) ----
#pragma unroll
    for (int i = 0; i < 32; i++) {
        const int k2 = ((i & 1) << 4) | ((i & 2) << 2) | (i & 4) |
                       ((i & 8) >> 2) | ((i & 16) >> 4);
        __stcs(&yb[lane + 32 * k2], make_float2(ar[i], ai[i]));
    }
}

extern "C" void kernel_launch(void* const* d_in, const int* in_sizes, int n_in,
                              void* d_out, int out_size)
{
    const float* x = (const float*)d_in[0];
    float* y = (float*)d_out;
    const int B = in_sizes[0] / 2048;  // 1024 complex (2048 floats) per row
    fft1024_kernel<<<B / WARPS_PER_CTA, THREADS>>>(x, y);
}

// round 3
// speedup vs baseline: 1.3728x; 1.0672x over previous
#include <cuda_runtime.h>

#define THREADS 128   // 2 rows per CTA, 64 lanes (2 warps) per row

// ---- compile-time twiddle tables ----
// TW16: e^{-2*pi*i*k/16}, k=0..7   (radix-2 fft16 stage twiddles)
__device__ __constant__ float kDummy; // keep nvcc happy about empty const seg

__device__ __forceinline__ void cmul_acc(float& rr, float& ri,
                                         float ar, float ai, float br, float bi) {
    rr = fmaf(ar, br, -ai * bi);
    ri = fmaf(ar, bi,  ai * br);
}

// 16-point radix-2 DIF FFT in registers. Natural-order input,
// bit-reversed output: reg j holds X[br4(j)].
__device__ __forceinline__ void fft16(float* ar, float* ai)
{
    constexpr float TC[8] = { 1.0f, 0.92387953251128674f, 0.70710678118654752f,
                              0.38268343236508977f, 0.0f, -0.38268343236508977f,
                             -0.70710678118654752f, -0.92387953251128674f };
    constexpr float TS[8] = { 0.0f, -0.38268343236508977f, -0.70710678118654752f,
                             -0.92387953251128674f, -1.0f, -0.92387953251128674f,
                             -0.70710678118654752f, -0.38268343236508977f };
#pragma unroll
    for (int s = 0; s < 4; s++) {
        const int span = 8 >> s;
        const int tstep = 1 << s;
#pragma unroll
        for (int b = 0; b < 16; b += 2 * span) {
#pragma unroll
            for (int j = 0; j < span; j++) {
                const int i0 = b + j, i1 = b + j + span;
                float ur = ar[i0], ui = ai[i0];
                float vr = ar[i1], vi = ai[i1];
                ar[i0] = ur + vr;
                ai[i0] = ui + vi;
                float dr = ur - vr, di = ui - vi;
                const float wr = TC[j * tstep], wi = TS[j * tstep];
                ar[i1] = dr * wr - di * wi;
                ai[i1] = dr * wi + di * wr;
            }
        }
    }
}

// Combine two half-FFTs (even/odd split across lane pair l <-> l^16) into a
// 32-pt FFT via shfl. Lane h=0 holds E[K], h=1 holds O[K], K=br4(j).
// After: lane h holds X32[h*16 + br4(j)].
__device__ __forceinline__ void combine32(float* ar, float* ai, int h)
{
    constexpr float WC[16] = { 1.0f, 0.98078528040323044f, 0.92387953251128674f,
        0.83146961230254524f, 0.70710678118654752f, 0.55557023301960222f,
        0.38268343236508977f, 0.19509032201612827f, 0.0f, -0.19509032201612827f,
       -0.38268343236508977f, -0.55557023301960222f, -0.70710678118654752f,
       -0.83146961230254524f, -0.92387953251128674f, -0.98078528040323044f };
    constexpr float WS[16] = { 0.0f, -0.19509032201612827f, -0.38268343236508977f,
       -0.55557023301960222f, -0.70710678118654752f, -0.83146961230254524f,
       -0.92387953251128674f, -0.98078528040323044f, -1.0f, -0.98078528040323044f,
       -0.92387953251128674f, -0.83146961230254524f, -0.70710678118654752f,
       -0.55557023301960222f, -0.38268343236508977f, -0.19509032201612827f };

    const float sgn = h ? -1.0f : 1.0f;
#pragma unroll
    for (int j = 0; j < 16; j++) {
        const int K = ((j & 1) << 3) | ((j & 2) << 1) | ((j & 4) >> 1) | ((j & 8) >> 3);
        float br = __shfl_xor_sync(0xffffffffu, ar[j], 16);
        float bi = __shfl_xor_sync(0xffffffffu, ai[j], 16);
        // E = own for h=0, partner for h=1; O = the other one
        float er = h ? br : ar[j];
        float ei = h ? bi : ai[j];
        float pr = h ? ar[j] : br;
        float pi = h ? ai[j] : bi;
        float tr, ti;
        cmul_acc(tr, ti, pr, pi, WC[K], WS[K]);
        ar[j] = fmaf(sgn, tr, er);
        ai[j] = fmaf(sgn, ti, ei);
    }
}

// Four-step 1024 = 32 x 32. 64 lanes (2 warps) per row, 2 rows per CTA.
// Each 32-pt sub-FFT is done by a lane pair: fft16 per lane + shfl combine.
__global__ void __launch_bounds__(THREADS, 8) fft1024_kernel(
    const float* __restrict__ xin, float* __restrict__ xout)
{
    __shared__ float sre[2][32 * 33];
    __shared__ float sim[2][32 * 33];

    const int tid = threadIdx.x;
    const int r = tid >> 6;          // row within CTA (0/1)
    const int w = (tid >> 5) & 1;    // warp-half of the row
    const int l = tid & 31;
    const int h = l >> 4;            // even/odd sample half
    const int q = l & 15;

    const int row = blockIdx.x * 2 + r;
    const float2* __restrict__ xb =
        reinterpret_cast<const float2*>(xin) + (size_t)row * 1024;
    float2* __restrict__ yb =
        reinterpret_cast<float2*>(xout) + (size_t)row * 1024;

    float ar[16], ai[16];

    // ================= Phase A: column FFTs over n2, column n1 =============
    const int n1 = w * 16 + q;
#pragma unroll
    for (int j = 0; j < 16; j++) {
        float2 v = __ldcs(&xb[(2 * j + h) * 32 + n1]);
        ar[j] = v.x;
        ai[j] = v.y;
    }
    fft16(ar, ai);
    combine32(ar, ai, h);   // lane holds Y[n1][k1], k1 = h*16 + br4(j)

    // inter-phase twiddle W1024^(n1*k1), store transposed smem[k1][n1]
    const float base = -6.2831853071795864769e0f / 1024.0f * (float)n1;
#pragma unroll
    for (int j = 0; j < 16; j++) {
        const int k1 = h * 16 +
            (((j & 1) << 3) | ((j & 2) << 1) | ((j & 4) >> 1) | ((j & 8) >> 3));
        float s, c;
        __sincosf(base * (float)k1, &s, &c);
        float tr, ti;
        cmul_acc(tr, ti, ar[j], ai[j], c, s);
        sre[r][k1 * 33 + n1] = tr;
        sim[r][k1 * 33 + n1] = ti;
    }
    __syncthreads();

    // ================= Phase B: row FFTs over n1, row k1 ====================
    const int k1b = w * 16 + q;
#pragma unroll
    for (int j = 0; j < 16; j++) {
        ar[j] = sre[r][k1b * 33 + (2 * j + h)];
        ai[j] = sim[r][k1b * 33 + (2 * j + h)];
    }
    fft16(ar, ai);
    combine32(ar, ai, h);   // lane holds X[k1b + 32*k2], k2 = h*16 + br4(j)

#pragma unroll
    for (int j = 0; j < 16; j++) {
        const int k2 = h * 16 +
            (((j & 1) << 3) | ((j & 2) << 1) | ((j & 4) >> 1) | ((j & 8) >> 3));
        __stcs(&yb[k1b + 32 * k2], make_float2(ar[j], ai[j]));
    }
}

extern "C" void kernel_launch(void* const* d_in, const int* in_sizes, int n_in,
                              void* d_out, int out_size)
{
    const float* x = (const float*)d_in[0];
    float* y = (float*)d_out;
    const int B = in_sizes[0] / 2048;   // 1024 complex per row
    fft1024_kernel<<<B / 2, THREADS>>>(x, y);
}